// round 2
// baseline (speedup 1.0000x reference)
#include <cuda_runtime.h>
#include <cstdint>

// ============================================================================
// out[4096,1000] = core[4096,4096] @ weights[1000,4096]^T   (fp32)
//
// tcgen05 is compile-gated off (harness PTX target is sm_103 base, all
// tcgen05.* are 'a'-feature instructions). Fall back to mma.sync tf32
// (HMMA, sm_80+ path): 256x128 CTA tile, BK=16, 4-stage cp.async pipeline,
// 8 warps x (64x64) register accumulators, explicit cvt.rna.tf32 rounding.
// ============================================================================

#define MDIM 4096
#define NDIM 1000
#define KDIM 4096

#define BM 256
#define BN 128
#define BK 16
#define BKP 20                      // padded row length (floats): conflict-free LDS
#define STAGES 4
#define KTILES (KDIM / BK)          // 256
#define THREADS 256

#define A_STG (BM * BKP)            // 5120 floats
#define B_STG (BN * BKP)            // 2560 floats
#define STG (A_STG + B_STG)         // 7680 floats
#define SMEM_BYTES (STAGES * STG * 4)   // 122880 B

// ---------------------------------------------------------------------------
__device__ __forceinline__ uint32_t smem_u32(const void* p) {
    uint32_t a;
    asm("{ .reg .u64 t; cvta.to.shared.u64 t, %1; cvt.u32.u64 %0, t; }" : "=r"(a) : "l"(p));
    return a;
}

__device__ __forceinline__ void cp16(uint32_t dst, const float* src, uint32_t src_bytes) {
    asm volatile("cp.async.cg.shared.global [%0], [%1], 16, %2;"
                 :: "r"(dst), "l"(src), "r"(src_bytes) : "memory");
}
#define CP_COMMIT() asm volatile("cp.async.commit_group;" ::: "memory")
#define CP_WAIT2()  asm volatile("cp.async.wait_group 2;"  ::: "memory")

__device__ __forceinline__ uint32_t f2tf(float f) {
    uint32_t r;
    asm("cvt.rna.tf32.f32 %0, %1;" : "=r"(r) : "f"(f));
    return r;
}

__device__ __forceinline__ void mma_tf32(float c[4],
                                         const uint32_t a[4], const uint32_t b[2]) {
    asm volatile(
        "mma.sync.aligned.m16n8k8.row.col.f32.tf32.tf32.f32 "
        "{%0,%1,%2,%3}, {%4,%5,%6,%7}, {%8,%9}, {%0,%1,%2,%3};"
        : "+f"(c[0]), "+f"(c[1]), "+f"(c[2]), "+f"(c[3])
        : "r"(a[0]), "r"(a[1]), "r"(a[2]), "r"(a[3]), "r"(b[0]), "r"(b[1]));
}

// ---------------------------------------------------------------------------
__global__ void __launch_bounds__(THREADS, 1)
tol_gemm_tf32(const float* __restrict__ A,     // [4096, 4096]
              const float* __restrict__ Bw,    // [1000, 4096]
              float* __restrict__ C) {         // [4096, 1000]
    extern __shared__ float smem[];
    const int tid  = threadIdx.x;
    const int wid  = tid >> 5;
    const int lane = tid & 31;

    const int m0 = blockIdx.y * BM;
    const int n0 = blockIdx.x * BN;

    const int warp_m = wid >> 1;     // 0..3  (64-row band)
    const int warp_n = wid & 1;      // 0..1  (64-col band)

    // global->smem load mapping: each thread copies 16B chunks
    const int lrow = tid >> 2;       // 0..63
    const int lc4  = tid & 3;        // 0..3  (which 16B of the 64B row)
    const uint32_t sb = smem_u32(smem);

    const float* agbase = A  + (size_t)(m0 + lrow) * KDIM + lc4 * 4;
    // clamp B row address (src_bytes=0 zero-fills, keep the address in-range)
    int brow0 = n0 + lrow;
    int brow1 = n0 + lrow + 64;
    const uint32_t bok0 = (brow0 < NDIM) ? 16u : 0u;
    const uint32_t bok1 = (brow1 < NDIM) ? 16u : 0u;
    if (brow0 >= NDIM) brow0 = NDIM - 1;
    if (brow1 >= NDIM) brow1 = NDIM - 1;
    const float* bg0 = Bw + (size_t)brow0 * KDIM + lc4 * 4;
    const float* bg1 = Bw + (size_t)brow1 * KDIM + lc4 * 4;

    const uint32_t a_dst0 = sb + (uint32_t)(lrow * BKP + lc4 * 4) * 4;
    const uint32_t b_dst0 = sb + (uint32_t)(A_STG + lrow * BKP + lc4 * 4) * 4;

#define ISSUE_STAGE(kt, s) do {                                                 \
        const uint32_t soff = (uint32_t)(s) * (STG * 4);                        \
        const size_t  koff  = (size_t)(kt) * BK;                                \
        _Pragma("unroll")                                                       \
        for (int i = 0; i < 4; i++)                                             \
            cp16(a_dst0 + soff + (uint32_t)(i * 64 * BKP * 4),                  \
                 agbase + koff + (size_t)i * 64 * KDIM, 16);                    \
        cp16(b_dst0 + soff, bg0 + koff, bok0);                                  \
        cp16(b_dst0 + soff + (uint32_t)(64 * BKP * 4), bg1 + koff, bok1);       \
    } while (0)

    float acc[4][8][4];
    #pragma unroll
    for (int t = 0; t < 4; t++)
        #pragma unroll
        for (int u = 0; u < 8; u++)
            #pragma unroll
            for (int i = 0; i < 4; i++)
                acc[t][u][i] = 0.0f;

    // prologue: fill STAGES-1 stages
    #pragma unroll
    for (int p = 0; p < STAGES - 1; p++) {
        ISSUE_STAGE(p, p);
        CP_COMMIT();
    }

    const int ar0 = warp_m * 64 + (lane >> 2);   // A row within tile (+t*16, +8)
    const int ac0 = lane & 3;                    // A col within k-chunk (+ks*8, +4)
    const int bn0 = warp_n * 64 + (lane >> 2);   // B row (n) within tile (+u*8)

    for (int kt = 0; kt < KTILES; kt++) {
        const int s = kt & (STAGES - 1);
        CP_WAIT2();
        __syncthreads();

        const float* as = smem + s * STG;
        const float* bs = as + A_STG;

        #pragma unroll
        for (int ks = 0; ks < 2; ks++) {
            uint32_t af[4][4];
            #pragma unroll
            for (int t = 0; t < 4; t++) {
                const float* p = as + (ar0 + t * 16) * BKP + ks * 8 + ac0;
                af[t][0] = f2tf(p[0]);
                af[t][1] = f2tf(p[8 * BKP]);
                af[t][2] = f2tf(p[4]);
                af[t][3] = f2tf(p[8 * BKP + 4]);
            }
            uint32_t bf[8][2];
            #pragma unroll
            for (int u = 0; u < 8; u++) {
                const float* p = bs + (bn0 + u * 8) * BKP + ks * 8 + ac0;
                bf[u][0] = f2tf(p[0]);
                bf[u][1] = f2tf(p[4]);
            }
            #pragma unroll
            for (int t = 0; t < 4; t++)
                #pragma unroll
                for (int u = 0; u < 8; u++)
                    mma_tf32(acc[t][u], af[t], bf[u]);
        }

        const int kn = kt + STAGES - 1;
        if (kn < KTILES) {
            ISSUE_STAGE(kn, kn & (STAGES - 1));
        }
        CP_COMMIT();
    }

    // ---- epilogue: write 64x64 accumulators, guard N edge (1000) ----
    #pragma unroll
    for (int t = 0; t < 4; t++) {
        const int gr = m0 + warp_m * 64 + t * 16 + (lane >> 2);
        #pragma unroll
        for (int u = 0; u < 8; u++) {
            const int gc = n0 + warp_n * 64 + u * 8 + (lane & 3) * 2;
            if (gc < NDIM) {   // NDIM even; float2 never straddles the edge
                float2 v0 = make_float2(acc[t][u][0], acc[t][u][1]);
                float2 v1 = make_float2(acc[t][u][2], acc[t][u][3]);
                *reinterpret_cast<float2*>(C + (size_t)gr * NDIM + gc) = v0;
                *reinterpret_cast<float2*>(C + (size_t)(gr + 8) * NDIM + gc) = v1;
            }
        }
    }
}

// ---------------------------------------------------------------------------
extern "C" void kernel_launch(void* const* d_in, const int* in_sizes, int n_in,
                              void* d_out, int out_size) {
    const float* core = (const float*)d_in[0];   // [4096, 16,16,16] = [4096,4096]
    const float* wts  = (const float*)d_in[1];   // [1000, 4096]
    float* out = (float*)d_out;                  // [4096, 1000]

    cudaFuncSetAttribute(tol_gemm_tf32,
                         cudaFuncAttributeMaxDynamicSharedMemorySize, SMEM_BYTES);

    dim3 grid((NDIM + BN - 1) / BN, MDIM / BM, 1);   // (8, 16) = 128 CTAs
    tol_gemm_tf32<<<grid, THREADS, SMEM_BYTES>>>(core, wts, out);
}